// round 2
// baseline (speedup 1.0000x reference)
#include <cuda_runtime.h>
#include <math.h>

// Problem constants (fixed by reference setup)
#define BD     16      // batch
#define HD     16      // heads
#define DD     128     // head dim
#define BLKD   16      // tokens per cache block
#define MAXBD  128     // blocks per sequence
#define MAXSD  2048    // max sequence length
#define NSPLIT 16      // KV splits per (b,h)
#define CHUNK  (MAXSD / NSPLIT)   // 128 tokens per split
#define SOFTMAX_SCALE 0.088388347648318447f  // 1/sqrt(128)

// Partial-result scratch (allocation-free: __device__ globals)
__device__ float g_pm[BD * HD * NSPLIT];
__device__ float g_pl[BD * HD * NSPLIT];
__device__ float g_pacc[BD * HD * NSPLIT * DD];   // 2 MB

// ---------------------------------------------------------------------------
// Pass 1: per (b, h, split) compute online-softmax partial over its 128 tokens.
// 128 threads = 4 warps; each warp owns tokens s0+warp, s0+warp+4, ...
// Each lane holds a float4 slice of the D=128 dimension.
// The fresh token lives at s == input_length-1; there we substitute the
// freshly-roped K and raw V from registers (the reference scatters them into
// the cache before reading it back). This avoids depending on save_slots'
// dtype entirely.
// ---------------------------------------------------------------------------
__global__ __launch_bounds__(128) void attn_pass1(
    const float* __restrict__ Q,  const float* __restrict__ K,
    const float* __restrict__ V,  const float* __restrict__ Kc,
    const float* __restrict__ Vc, const float* __restrict__ cosb,
    const float* __restrict__ sinb, const float* __restrict__ mask,
    const int* __restrict__ ilen, const int* __restrict__ btab)
{
    const int split = blockIdx.x, h = blockIdx.y, b = blockIdx.z;
    const int tid = threadIdx.x, warp = tid >> 5, lane = tid & 31;
    const int pidx = (b * HD + h) * NSPLIT + split;
    const int L = ilen[b];
    const int s0 = split * CHUNK;

    if (s0 >= L) {  // empty split: write neutral partial
        if (tid == 0) { g_pm[pidx] = -INFINITY; g_pl[pidx] = 0.f; }
        g_pacc[pidx * DD + tid] = 0.f;
        return;
    }
    const int s1  = (s0 + CHUNK < L) ? s0 + CHUNK : L;
    const int pos = L - 1;   // fresh-token position

    // --- RoPE on Q and K (registers) ---
    const float4 q4  = *(const float4*)(Q    + (b * HD + h) * DD + 4 * lane);
    const float4 k4  = *(const float4*)(K    + (b * HD + h) * DD + 4 * lane);
    const float4 vv4 = *(const float4*)(V    + (b * HD + h) * DD + 4 * lane);
    const float4 c4  = *(const float4*)(cosb + b * DD + 4 * lane);
    const float4 s4  = *(const float4*)(sinb + b * DD + 4 * lane);

    // rot = concat(-x[64:], x[:64]); partner dims live at lane^16
    const float sgn = (lane < 16) ? -1.f : 1.f;
    float4 qp, kp;
    qp.x = __shfl_xor_sync(0xffffffffu, q4.x, 16);
    qp.y = __shfl_xor_sync(0xffffffffu, q4.y, 16);
    qp.z = __shfl_xor_sync(0xffffffffu, q4.z, 16);
    qp.w = __shfl_xor_sync(0xffffffffu, q4.w, 16);
    kp.x = __shfl_xor_sync(0xffffffffu, k4.x, 16);
    kp.y = __shfl_xor_sync(0xffffffffu, k4.y, 16);
    kp.z = __shfl_xor_sync(0xffffffffu, k4.z, 16);
    kp.w = __shfl_xor_sync(0xffffffffu, k4.w, 16);

    float4 qr, kr;   // qr pre-scaled by softmax scale
    qr.x = (q4.x * c4.x + sgn * qp.x * s4.x) * SOFTMAX_SCALE;
    qr.y = (q4.y * c4.y + sgn * qp.y * s4.y) * SOFTMAX_SCALE;
    qr.z = (q4.z * c4.z + sgn * qp.z * s4.z) * SOFTMAX_SCALE;
    qr.w = (q4.w * c4.w + sgn * qp.w * s4.w) * SOFTMAX_SCALE;
    kr.x =  k4.x * c4.x + sgn * kp.x * s4.x;
    kr.y =  k4.y * c4.y + sgn * kp.y * s4.y;
    kr.z =  k4.z * c4.z + sgn * kp.z * s4.z;
    kr.w =  k4.w * c4.w + sgn * kp.w * s4.w;

    const int*   bt = btab + b * MAXBD;
    const float* mk = mask + b * MAXSD;

    float m = -INFINITY, l = 0.f;
    float4 acc = make_float4(0.f, 0.f, 0.f, 0.f);

    for (int s = s0 + warp; s < s1; s += 4) {
        const int  row  = __ldg(bt + (s >> 4)) * BLKD + (s & 15);
        const bool spec = (s == pos);
        const int  off  = (row * HD + h) * DD + 4 * lane;

        float4 kk = spec ? kr  : __ldg((const float4*)(Kc + off));
        float4 vv = spec ? vv4 : __ldg((const float4*)(Vc + off));

        float dot = qr.x * kk.x + qr.y * kk.y + qr.z * kk.z + qr.w * kk.w;
        #pragma unroll
        for (int o = 16; o > 0; o >>= 1)
            dot += __shfl_xor_sync(0xffffffffu, dot, o);

        const float score = dot + __ldg(mk + s);
        const float mnew  = fmaxf(m, score);
        const float corr  = __expf(m - mnew);      // exp(-inf)=0 first iter
        const float p     = __expf(score - mnew);
        l = l * corr + p;
        acc.x = acc.x * corr + p * vv.x;
        acc.y = acc.y * corr + p * vv.y;
        acc.z = acc.z * corr + p * vv.z;
        acc.w = acc.w * corr + p * vv.w;
        m = mnew;
    }

    // --- combine the 4 warps' partials ---
    __shared__ float sm_m[4], sm_l[4], sm_a[4 * DD];
    float* dst = sm_a + warp * DD + 4 * lane;
    dst[0] = acc.x; dst[1] = acc.y; dst[2] = acc.z; dst[3] = acc.w;
    if (lane == 0) { sm_m[warp] = m; sm_l[warp] = l; }
    __syncthreads();

    const float M = fmaxf(fmaxf(sm_m[0], sm_m[1]), fmaxf(sm_m[2], sm_m[3]));
    float Lt = 0.f, a = 0.f;
    #pragma unroll
    for (int w = 0; w < 4; w++) {
        const float wl = sm_l[w];
        const float wf = (wl > 0.f) ? __expf(sm_m[w] - M) : 0.f;
        Lt += wf * wl;
        a  += wf * sm_a[w * DD + tid];
    }
    if (tid == 0) { g_pm[pidx] = M; g_pl[pidx] = Lt; }
    g_pacc[pidx * DD + tid] = a;
}

// ---------------------------------------------------------------------------
// Pass 2: combine the NSPLIT partials per (b, h) and normalize.
// ---------------------------------------------------------------------------
__global__ __launch_bounds__(128) void attn_pass2(float* __restrict__ out)
{
    const int h = blockIdx.x, b = blockIdx.y;
    const int tid = threadIdx.x;
    const int base = (b * HD + h) * NSPLIT;

    float M = -INFINITY;
    #pragma unroll
    for (int i = 0; i < NSPLIT; i++)
        if (g_pl[base + i] > 0.f) M = fmaxf(M, g_pm[base + i]);

    float Lt = 0.f, a = 0.f;
    #pragma unroll
    for (int i = 0; i < NSPLIT; i++) {
        const float li = g_pl[base + i];
        if (li > 0.f) {
            const float w = __expf(g_pm[base + i] - M);
            Lt += w * li;
            a  += w * g_pacc[(base + i) * DD + tid];
        }
    }
    out[(b * HD + h) * DD + tid] = a / Lt;
}

// ---------------------------------------------------------------------------
extern "C" void kernel_launch(void* const* d_in, const int* in_sizes, int n_in,
                              void* d_out, int out_size)
{
    const float* Q    = (const float*)d_in[0];
    const float* K    = (const float*)d_in[1];
    const float* V    = (const float*)d_in[2];
    const float* Kc   = (const float*)d_in[3];
    const float* Vc   = (const float*)d_in[4];
    const float* cosb = (const float*)d_in[5];
    const float* sinb = (const float*)d_in[6];
    const float* mask = (const float*)d_in[7];
    const int*   ilen = (const int*)d_in[8];
    // d_in[9] = save_slots (dtype-ambiguous; intentionally unused — the fresh
    // token position is input_length-1 by construction)
    const int*   btab = (const int*)d_in[10];
    (void)in_sizes; (void)n_in; (void)out_size;

    dim3 g1(NSPLIT, HD, BD);
    attn_pass1<<<g1, 128>>>(Q, K, V, Kc, Vc, cosb, sinb, mask, ilen, btab);
    attn_pass2<<<dim3(HD, BD), 128>>>((float*)d_out);
}

// round 3
// speedup vs baseline: 1.3462x; 1.3462x over previous
#include <cuda_runtime.h>
#include <math.h>

// Problem constants (fixed by reference setup)
#define BD     16      // batch
#define HD     16      // heads
#define DD     128     // head dim
#define BLKD   16      // tokens per cache block
#define MAXBD  128     // blocks per sequence
#define MAXSD  2048    // max sequence length
#define NSPLIT 16      // KV splits per (b,h)
#define CHUNK  (MAXSD / NSPLIT)   // 128 tokens per split
#define SOFTMAX_SCALE 0.088388347648318447f  // 1/sqrt(128)

// Partial-result scratch (allocation-free: __device__ globals, zero-init .bss)
__device__ float g_pm[BD * HD * NSPLIT];
__device__ float g_pl[BD * HD * NSPLIT];
__device__ float g_pacc[BD * HD * NSPLIT * DD];      // 2 MB
__device__ unsigned int g_cnt[BD * HD];              // self-resetting counters

// ---------------------------------------------------------------------------
// Fused split-KV decode attention:
//  grid (NSPLIT, HD, BD), 128 threads = 4 warps.
//  Each warp owns tokens s0+warp, +4, +8 ... ; each lane a float4 of D=128.
//  Token loop unrolled x4 (8 independent float4 loads in flight; 4 parallel
//  shuffle-reduce chains; group-max softmax -> 5 expf per 4 tokens).
//  Fresh token (s == L-1) substitutes register-roped K / raw V — reference
//  scatters them into the cache before the gather.
//  The LAST split CTA per (b,h) (threadfence reduction) combines the NSPLIT
//  partials and writes the output; it then resets the counter to 0 so every
//  graph replay starts from identical state.
// ---------------------------------------------------------------------------
__global__ __launch_bounds__(128) void attn_fused(
    const float* __restrict__ Q,  const float* __restrict__ K,
    const float* __restrict__ V,  const float* __restrict__ Kc,
    const float* __restrict__ Vc, const float* __restrict__ cosb,
    const float* __restrict__ sinb, const float* __restrict__ mask,
    const int* __restrict__ ilen, const int* __restrict__ btab,
    float* __restrict__ out)
{
    const int split = blockIdx.x, h = blockIdx.y, b = blockIdx.z;
    const int tid = threadIdx.x, warp = tid >> 5, lane = tid & 31;
    const int bh   = b * HD + h;
    const int pidx = bh * NSPLIT + split;
    const int L  = ilen[b];
    const int s0 = split * CHUNK;

    if (s0 < L) {
        const int s1  = (s0 + CHUNK < L) ? s0 + CHUNK : L;
        const int pos = L - 1;   // fresh-token position

        // --- RoPE on Q and K (registers) ---
        const float4 q4  = *(const float4*)(Q    + bh * DD + 4 * lane);
        const float4 k4  = *(const float4*)(K    + bh * DD + 4 * lane);
        const float4 vv4 = *(const float4*)(V    + bh * DD + 4 * lane);
        const float4 c4  = *(const float4*)(cosb + b * DD + 4 * lane);
        const float4 s4  = *(const float4*)(sinb + b * DD + 4 * lane);

        const float sgn = (lane < 16) ? -1.f : 1.f;   // rot = [-x2, x1]
        float4 qp, kp;
        qp.x = __shfl_xor_sync(~0u, q4.x, 16);  qp.y = __shfl_xor_sync(~0u, q4.y, 16);
        qp.z = __shfl_xor_sync(~0u, q4.z, 16);  qp.w = __shfl_xor_sync(~0u, q4.w, 16);
        kp.x = __shfl_xor_sync(~0u, k4.x, 16);  kp.y = __shfl_xor_sync(~0u, k4.y, 16);
        kp.z = __shfl_xor_sync(~0u, k4.z, 16);  kp.w = __shfl_xor_sync(~0u, k4.w, 16);

        float4 qr, kr;   // qr pre-scaled by softmax scale
        qr.x = (q4.x * c4.x + sgn * qp.x * s4.x) * SOFTMAX_SCALE;
        qr.y = (q4.y * c4.y + sgn * qp.y * s4.y) * SOFTMAX_SCALE;
        qr.z = (q4.z * c4.z + sgn * qp.z * s4.z) * SOFTMAX_SCALE;
        qr.w = (q4.w * c4.w + sgn * qp.w * s4.w) * SOFTMAX_SCALE;
        kr.x =  k4.x * c4.x + sgn * kp.x * s4.x;
        kr.y =  k4.y * c4.y + sgn * kp.y * s4.y;
        kr.z =  k4.z * c4.z + sgn * kp.z * s4.z;
        kr.w =  k4.w * c4.w + sgn * kp.w * s4.w;

        const int*   bt = btab + b * MAXBD;
        const float* mk = mask + b * MAXSD;

        float m = -INFINITY, l = 0.f;
        float4 acc = make_float4(0.f, 0.f, 0.f, 0.f);

        int s = s0 + warp;
        // ---- unrolled x4: tokens s, s+4, s+8, s+12 ----
        for (; s + 12 < s1; s += 16) {
            float4 kk[4], vv[4];
            float  dot[4];
            #pragma unroll
            for (int j = 0; j < 4; j++) {
                const int  t   = s + 4 * j;
                const int  row = __ldg(bt + (t >> 4)) * BLKD + (t & 15);
                const int  off = (row * HD + h) * DD + 4 * lane;
                const bool sp  = (t == pos);
                kk[j] = sp ? kr  : __ldg((const float4*)(Kc + off));
                vv[j] = sp ? vv4 : __ldg((const float4*)(Vc + off));
            }
            #pragma unroll
            for (int j = 0; j < 4; j++)
                dot[j] = qr.x * kk[j].x + qr.y * kk[j].y
                       + qr.z * kk[j].z + qr.w * kk[j].w;
            #pragma unroll
            for (int o = 16; o > 0; o >>= 1) {
                #pragma unroll
                for (int j = 0; j < 4; j++)
                    dot[j] += __shfl_xor_sync(~0u, dot[j], o);
            }
            float sc[4];
            #pragma unroll
            for (int j = 0; j < 4; j++) sc[j] = dot[j] + __ldg(mk + s + 4 * j);

            const float gm   = fmaxf(fmaxf(sc[0], sc[1]), fmaxf(sc[2], sc[3]));
            const float mnew = fmaxf(m, gm);
            const float corr = __expf(m - mnew);
            float p[4];
            #pragma unroll
            for (int j = 0; j < 4; j++) p[j] = __expf(sc[j] - mnew);

            l = l * corr + ((p[0] + p[1]) + (p[2] + p[3]));
            acc.x = acc.x * corr + (p[0]*vv[0].x + p[1]*vv[1].x + p[2]*vv[2].x + p[3]*vv[3].x);
            acc.y = acc.y * corr + (p[0]*vv[0].y + p[1]*vv[1].y + p[2]*vv[2].y + p[3]*vv[3].y);
            acc.z = acc.z * corr + (p[0]*vv[0].z + p[1]*vv[1].z + p[2]*vv[2].z + p[3]*vv[3].z);
            acc.w = acc.w * corr + (p[0]*vv[0].w + p[1]*vv[1].w + p[2]*vv[2].w + p[3]*vv[3].w);
            m = mnew;
        }
        // ---- scalar remainder ----
        for (; s < s1; s += 4) {
            const int  row = __ldg(bt + (s >> 4)) * BLKD + (s & 15);
            const int  off = (row * HD + h) * DD + 4 * lane;
            const bool sp  = (s == pos);
            const float4 kk = sp ? kr  : __ldg((const float4*)(Kc + off));
            const float4 vv = sp ? vv4 : __ldg((const float4*)(Vc + off));

            float dot = qr.x*kk.x + qr.y*kk.y + qr.z*kk.z + qr.w*kk.w;
            #pragma unroll
            for (int o = 16; o > 0; o >>= 1)
                dot += __shfl_xor_sync(~0u, dot, o);

            const float score = dot + __ldg(mk + s);
            const float mnew  = fmaxf(m, score);
            const float corr  = __expf(m - mnew);
            const float p     = __expf(score - mnew);
            l = l * corr + p;
            acc.x = acc.x * corr + p * vv.x;
            acc.y = acc.y * corr + p * vv.y;
            acc.z = acc.z * corr + p * vv.z;
            acc.w = acc.w * corr + p * vv.w;
            m = mnew;
        }

        // --- combine the 4 warps' partials ---
        __shared__ float sm_m[4], sm_l[4], sm_a[4 * DD];
        float* dst = sm_a + warp * DD + 4 * lane;
        dst[0] = acc.x; dst[1] = acc.y; dst[2] = acc.z; dst[3] = acc.w;
        if (lane == 0) { sm_m[warp] = m; sm_l[warp] = l; }
        __syncthreads();

        const float M = fmaxf(fmaxf(sm_m[0], sm_m[1]), fmaxf(sm_m[2], sm_m[3]));
        float Lt = 0.f, a = 0.f;
        #pragma unroll
        for (int w = 0; w < 4; w++) {
            const float wl = sm_l[w];
            const float wf = (wl > 0.f) ? __expf(sm_m[w] - M) : 0.f;
            Lt += wf * wl;
            a  += wf * sm_a[w * DD + tid];
        }
        if (tid == 0) { g_pm[pidx] = M; g_pl[pidx] = Lt; }
        g_pacc[pidx * DD + tid] = a;
    } else {
        // empty split: neutral partial
        if (tid == 0) { g_pm[pidx] = -INFINITY; g_pl[pidx] = 0.f; }
        g_pacc[pidx * DD + tid] = 0.f;
    }

    // --- threadfence reduction: last split CTA combines & writes output ---
    __shared__ unsigned int s_last;
    __threadfence();
    __syncthreads();
    if (tid == 0)
        s_last = (atomicAdd(&g_cnt[bh], 1u) == NSPLIT - 1u) ? 1u : 0u;
    __syncthreads();

    if (s_last) {
        const int base = bh * NSPLIT;
        float M = -INFINITY;
        #pragma unroll
        for (int i = 0; i < NSPLIT; i++)
            if (g_pl[base + i] > 0.f) M = fmaxf(M, g_pm[base + i]);

        float Lt = 0.f, a = 0.f;
        #pragma unroll
        for (int i = 0; i < NSPLIT; i++) {
            const float li = g_pl[base + i];
            if (li > 0.f) {
                const float w = __expf(g_pm[base + i] - M);
                Lt += w * li;
                a  += w * g_pacc[(base + i) * DD + tid];
            }
        }
        out[bh * DD + tid] = a / Lt;
        if (tid == 0) g_cnt[bh] = 0u;   // self-reset for next graph replay
    }
}

// ---------------------------------------------------------------------------
extern "C" void kernel_launch(void* const* d_in, const int* in_sizes, int n_in,
                              void* d_out, int out_size)
{
    const float* Q    = (const float*)d_in[0];
    const float* K    = (const float*)d_in[1];
    const float* V    = (const float*)d_in[2];
    const float* Kc   = (const float*)d_in[3];
    const float* Vc   = (const float*)d_in[4];
    const float* cosb = (const float*)d_in[5];
    const float* sinb = (const float*)d_in[6];
    const float* mask = (const float*)d_in[7];
    const int*   ilen = (const int*)d_in[8];
    // d_in[9] = save_slots — unused (fresh token is at input_length-1)
    const int*   btab = (const int*)d_in[10];
    (void)in_sizes; (void)n_in; (void)out_size;

    dim3 g1(NSPLIT, HD, BD);
    attn_fused<<<g1, 128>>>(Q, K, V, Kc, Vc, cosb, sinb, mask, ilen, btab,
                            (float*)d_out);
}